// round 16
// baseline (speedup 1.0000x reference)
#include <cuda_runtime.h>
#include <cuda_bf16.h>
#include <cstdint>

// Problem dims (fixed by the dataset)
#define B_ROWS 16384
#define S_DIM  512
#define H_DIM  1024
#define N_DIM  24
#define M_TOT  60      // 4 eq + 8 ineq + 24 (I) + 24 (-I)

// ---------------------------------------------------------------------------
// Device-global scratch (sanctioned: no allocation allowed)
// ---------------------------------------------------------------------------
__device__ __nv_bfloat16 g_sh[B_ROWS * S_DIM];
__device__ __nv_bfloat16 g_sl[B_ROWS * S_DIM];
__device__ __nv_bfloat16 g_h1h[B_ROWS * H_DIM];
__device__ __nv_bfloat16 g_h1l[B_ROWS * H_DIM];
__device__ __nv_bfloat16 g_h2h[B_ROWS * H_DIM];
__device__ __nv_bfloat16 g_h2l[B_ROWS * H_DIM];
__device__ __nv_bfloat16 g_w1h[H_DIM * S_DIM];
__device__ __nv_bfloat16 g_w1l[H_DIM * S_DIM];
__device__ __nv_bfloat16 g_w2h[H_DIM * H_DIM];
__device__ __nv_bfloat16 g_w2l[H_DIM * H_DIM];
__device__ __nv_bfloat16 g_w3h[32 * H_DIM];
__device__ __nv_bfloat16 g_w3l[32 * H_DIM];
__device__ float g_raw[B_ROWS * N_DIM];

// ADMM precomputed small matrices
__device__ float g_Atot[M_TOT * N_DIM];
__device__ float g_G[M_TOT * N_DIM];
__device__ float g_l[M_TOT];
__device__ float g_u[M_TOT];
__device__ float g_Minv[N_DIM * N_DIM];

// ---------------------------------------------------------------------------
// Helpers
// ---------------------------------------------------------------------------
__device__ __forceinline__ uint32_t smem_u32(const void* p) {
    uint32_t a;
    asm("{ .reg .u64 t; cvta.to.shared.u64 t, %1; cvt.u32.u64 %0, t; }"
        : "=r"(a) : "l"(p));
    return a;
}

#define SMEM_SWIZZLE_128B(x) ((x) ^ (((x) >> 3) & 0x70))

#define LDSM_X4(d0, d1, d2, d3, addr) \
    asm volatile("ldmatrix.sync.aligned.m8n8.x4.shared.b16 {%0,%1,%2,%3}, [%4];" \
        : "=r"(d0), "=r"(d1), "=r"(d2), "=r"(d3) : "r"(addr))

#define MMA_BF16(c, a, b) \
    asm volatile("mma.sync.aligned.m16n8k16.row.col.f32.bf16.bf16.f32 " \
        "{%0,%1,%2,%3}, {%4,%5,%6,%7}, {%8,%9}, {%0,%1,%2,%3};" \
        : "+f"((c)[0]), "+f"((c)[1]), "+f"((c)[2]), "+f"((c)[3]) \
        : "r"((a)[0]), "r"((a)[1]), "r"((a)[2]), "r"((a)[3]), \
          "r"((b)[0]), "r"((b)[1]))

__device__ __forceinline__ void split_bf16(float v, __nv_bfloat16& h, __nv_bfloat16& l) {
    h = __float2bfloat16(v);
    l = __float2bfloat16(v - __bfloat162float(h));
}

// ---------------------------------------------------------------------------
// Pre-pass 1: elementwise split fp32 -> (hi, lo) bf16
// ---------------------------------------------------------------------------
__global__ __launch_bounds__(256) void split_kernel(const float* __restrict__ X,
                                                    __nv_bfloat16* __restrict__ Xh,
                                                    __nv_bfloat16* __restrict__ Xl)
{
    int i = blockIdx.x * 256 + threadIdx.x;
    float4 v = ((const float4*)X)[i];
    __nv_bfloat16 h[4], l[4];
    split_bf16(v.x, h[0], l[0]); split_bf16(v.y, h[1], l[1]);
    split_bf16(v.z, h[2], l[2]); split_bf16(v.w, h[3], l[3]);
    ((uint2*)Xh)[i] = *(uint2*)h;
    ((uint2*)Xl)[i] = *(uint2*)l;
}

// ---------------------------------------------------------------------------
// Pre-pass 2: W [K x N] fp32 -> W^T [Npad x K] (hi, lo) bf16, zero-padded rows
// ---------------------------------------------------------------------------
__global__ __launch_bounds__(256) void transpose_split(const float* __restrict__ W,
                                                       __nv_bfloat16* __restrict__ Th,
                                                       __nv_bfloat16* __restrict__ Tl,
                                                       int K, int N, int Npad)
{
    __shared__ float t[32][33];
    int kb = blockIdx.x * 32, nb = blockIdx.y * 32;
    int tx = threadIdx.x & 31, ty = threadIdx.x >> 5;
#pragma unroll
    for (int i = 0; i < 32; i += 8) {
        int k = kb + ty + i, n = nb + tx;
        t[ty + i][tx] = (n < N) ? W[(size_t)k * N + n] : 0.0f;
    }
    __syncthreads();
#pragma unroll
    for (int i = 0; i < 32; i += 8) {
        int n = nb + ty + i, k = kb + tx;
        if (n < Npad) {
            float v = t[tx][ty + i];
            __nv_bfloat16 h, l;
            split_bf16(v, h, l);
            Th[(size_t)n * K + k] = h;
            Tl[(size_t)n * K + k] = l;
        }
    }
}

// ---------------------------------------------------------------------------
// Setup (unchanged — proven)
// ---------------------------------------------------------------------------
__global__ __launch_bounds__(256) void setup_kernel(const float* __restrict__ Aeq,
                             const float* __restrict__ beq,
                             const float* __restrict__ Ain,
                             const float* __restrict__ bin,
                             const float* __restrict__ ub,
                             const float* __restrict__ lb)
{
    __shared__ float At[M_TOT * N_DIM];
    __shared__ float Maug[24][49];
    const int tid = threadIdx.x;

    for (int s = tid; s < M_TOT * N_DIM; s += 256) {
        int i = s / N_DIM, j = s % N_DIM;
        float v;
        if (i < 4)       v = Aeq[i * N_DIM + j];
        else if (i < 12) v = Ain[(i - 4) * N_DIM + j];
        else if (i < 36) v = (j == i - 12) ? 1.0f : 0.0f;
        else             v = (j == i - 36) ? -1.0f : 0.0f;
        At[s] = v;
        g_Atot[s] = v;
    }
    if (tid < M_TOT) {
        int i = tid;
        float lv, uv;
        const float NEG_INF = __int_as_float(0xff800000);
        if (i < 4)       { lv = beq[i];        uv = beq[i]; }
        else if (i < 12) { lv = NEG_INF;       uv = bin[i - 4]; }
        else if (i < 36) { lv = lb[i - 12];    uv = ub[i - 12]; }
        else             { lv = -ub[i - 36];   uv = -lb[i - 36]; }
        g_l[i] = lv; g_u[i] = uv;
    }
    __syncthreads();

    for (int s = tid; s < N_DIM * N_DIM; s += 256) {
        int j = s / N_DIM, k = s % N_DIM;
        float sum = 0.0f;
        for (int i = 0; i < M_TOT; i++)
            sum += At[i * N_DIM + j] * At[i * N_DIM + k];
        if (j == k) sum += 1.0f + 1e-6f;
        Maug[j][k] = sum;
        Maug[j][24 + k] = (j == k) ? 1.0f : 0.0f;
    }
    __syncthreads();

    for (int k = 0; k < 24; k++) {
        if (tid == 0) {
            float piv = 1.0f / Maug[k][k];
            for (int c = 0; c < 48; c++) Maug[k][c] *= piv;
        }
        __syncthreads();
        if (tid < 24 && tid != k) {
            float f = Maug[tid][k];
            for (int c = 0; c < 48; c++) Maug[tid][c] -= f * Maug[k][c];
        }
        __syncthreads();
    }

    for (int s = tid; s < N_DIM * N_DIM; s += 256)
        g_Minv[s] = Maug[s / N_DIM][24 + (s % N_DIM)];

    for (int s = tid; s < M_TOT * N_DIM; s += 256) {
        int i = s / N_DIM, j = s % N_DIM;
        float sum = 0.0f;
        for (int k = 0; k < 24; k++)
            sum += At[i * N_DIM + k] * Maug[j][24 + k];
        g_G[s] = sum;
    }
}

// ---------------------------------------------------------------------------
// HMMA GEMM (mma.sync.m16n8k16 bf16), 2-split / 3-product, fp32 reg accum.
//   R15 proven version: LDG->reg->STS double buffering, single smem buffer.
// ---------------------------------------------------------------------------
template <int BN, bool RELUSPLIT>
__global__ __launch_bounds__(256) void gemm_mma(
    const __nv_bfloat16* __restrict__ Ahi, const __nv_bfloat16* __restrict__ Alo,
    const __nv_bfloat16* __restrict__ Bhi, const __nv_bfloat16* __restrict__ Blo,
    const float* __restrict__ bias,
    __nv_bfloat16* __restrict__ Ohi, __nv_bfloat16* __restrict__ Olo,
    float* __restrict__ Of32,
    int K)
{
    extern __shared__ __align__(1024) char sm[];
    constexpr int NF = BN / 16;
    constexpr int NBI = BN / 32;                       // B-tile iters per split
    __nv_bfloat16* As_h = (__nv_bfloat16*)sm;          // 128 x 64
    __nv_bfloat16* As_l = As_h + 128 * 64;
    __nv_bfloat16* Bs_h = As_l + 128 * 64;             // BN x 64
    __nv_bfloat16* Bs_l = Bs_h + BN * 64;

    const int tid  = threadIdx.x;
    const int wid  = tid >> 5;
    const int lane = tid & 31;
    const int m0 = blockIdx.y * 128;
    const int n0 = blockIdx.x * BN;
    const int m0w = (wid >> 1) * 32;
    const int n0w = (wid & 1) * (BN / 2);

    const uint32_t sAh = smem_u32(As_h), sAl = smem_u32(As_l);
    const uint32_t sBh = smem_u32(Bs_h), sBl = smem_u32(Bs_l);

    float acc[2][NF][4];
#pragma unroll
    for (int mf = 0; mf < 2; mf++)
#pragma unroll
        for (int nf = 0; nf < NF; nf++)
#pragma unroll
            for (int e = 0; e < 4; e++) acc[mf][nf][e] = 0.0f;

    const int r  = lane & 7;
    const int ms = lane >> 3;

    // per-thread staging registers for the next chunk
    uint4 ra_h[4], ra_l[4], rb_h[NBI], rb_l[NBI];

    auto ldg_chunk = [&](int kt) {
#pragma unroll
        for (int it = 0; it < 4; it++) {
            int idx = tid + it * 256;
            int row = idx >> 3, s16 = idx & 7;
            size_t g = (size_t)(m0 + row) * K + kt + s16 * 8;
            ra_h[it] = *(const uint4*)(Ahi + g);
            ra_l[it] = *(const uint4*)(Alo + g);
        }
#pragma unroll
        for (int it = 0; it < NBI; it++) {
            int idx = tid + it * 256;
            int row = idx >> 3, s16 = idx & 7;
            size_t g = (size_t)(n0 + row) * K + kt + s16 * 8;
            rb_h[it] = *(const uint4*)(Bhi + g);
            rb_l[it] = *(const uint4*)(Blo + g);
        }
    };

    auto sts_chunk = [&]() {
#pragma unroll
        for (int it = 0; it < 4; it++) {
            int idx = tid + it * 256;
            int row = idx >> 3, s16 = idx & 7;
            uint32_t off = SMEM_SWIZZLE_128B((uint32_t)(row * 128 + s16 * 16));
            *(uint4*)((char*)As_h + off) = ra_h[it];
            *(uint4*)((char*)As_l + off) = ra_l[it];
        }
#pragma unroll
        for (int it = 0; it < NBI; it++) {
            int idx = tid + it * 256;
            int row = idx >> 3, s16 = idx & 7;
            uint32_t off = SMEM_SWIZZLE_128B((uint32_t)(row * 128 + s16 * 16));
            *(uint4*)((char*)Bs_h + off) = rb_h[it];
            *(uint4*)((char*)Bs_l + off) = rb_l[it];
        }
    };

    ldg_chunk(0);

    for (int kt = 0; kt < K; kt += 64) {
        sts_chunk();
        __syncthreads();
        if (kt + 64 < K)
            ldg_chunk(kt + 64);   // issued now, consumed by STS next iter

#pragma unroll
        for (int ks = 0; ks < 4; ks++) {
            uint32_t a_h[2][4], a_l[2][4], bfr[NF][2];
#pragma unroll
            for (int mf = 0; mf < 2; mf++) {
                int row = m0w + mf * 16 + (ms & 1) * 8 + r;
                int seg = 2 * ks + (ms >> 1);
                uint32_t off = SMEM_SWIZZLE_128B((uint32_t)(row * 128 + seg * 16));
                LDSM_X4(a_h[mf][0], a_h[mf][1], a_h[mf][2], a_h[mf][3], sAh + off);
                LDSM_X4(a_l[mf][0], a_l[mf][1], a_l[mf][2], a_l[mf][3], sAl + off);
            }
#pragma unroll
            for (int g2 = 0; g2 < NF / 2; g2++) {
                int row = n0w + g2 * 16 + (ms >> 1) * 8 + r;
                int seg = 2 * ks + (ms & 1);
                uint32_t off = SMEM_SWIZZLE_128B((uint32_t)(row * 128 + seg * 16));
                LDSM_X4(bfr[2 * g2][0], bfr[2 * g2][1],
                        bfr[2 * g2 + 1][0], bfr[2 * g2 + 1][1], sBh + off);
            }
#pragma unroll
            for (int mf = 0; mf < 2; mf++)
#pragma unroll
                for (int nf = 0; nf < NF; nf++)
                    MMA_BF16(acc[mf][nf], a_h[mf], bfr[nf]);
#pragma unroll
            for (int mf = 0; mf < 2; mf++)
#pragma unroll
                for (int nf = 0; nf < NF; nf++)
                    MMA_BF16(acc[mf][nf], a_l[mf], bfr[nf]);
#pragma unroll
            for (int g2 = 0; g2 < NF / 2; g2++) {
                int row = n0w + g2 * 16 + (ms >> 1) * 8 + r;
                int seg = 2 * ks + (ms & 1);
                uint32_t off = SMEM_SWIZZLE_128B((uint32_t)(row * 128 + seg * 16));
                LDSM_X4(bfr[2 * g2][0], bfr[2 * g2][1],
                        bfr[2 * g2 + 1][0], bfr[2 * g2 + 1][1], sBl + off);
            }
#pragma unroll
            for (int mf = 0; mf < 2; mf++)
#pragma unroll
                for (int nf = 0; nf < NF; nf++)
                    MMA_BF16(acc[mf][nf], a_h[mf], bfr[nf]);
        }
        __syncthreads();
    }

    // ---- epilogue ----
    const int g = lane >> 2, q = lane & 3;
    if (RELUSPLIT) {
#pragma unroll
        for (int mf = 0; mf < 2; mf++) {
#pragma unroll
            for (int nf = 0; nf < NF; nf++) {
                int col = n0 + n0w + nf * 8 + q * 2;
                float b0 = bias[col], b1 = bias[col + 1];
                int row0 = m0 + m0w + mf * 16 + g;
#pragma unroll
                for (int h2 = 0; h2 < 2; h2++) {
                    int row = row0 + h2 * 8;
                    float v0 = fmaxf(acc[mf][nf][2 * h2 + 0] + b0, 0.0f);
                    float v1 = fmaxf(acc[mf][nf][2 * h2 + 1] + b1, 0.0f);
                    __nv_bfloat16 hh[2], ll[2];
                    split_bf16(v0, hh[0], ll[0]);
                    split_bf16(v1, hh[1], ll[1]);
                    size_t o = (size_t)row * H_DIM + col;
                    *(uint32_t*)(Ohi + o) = *(uint32_t*)hh;
                    *(uint32_t*)(Olo + o) = *(uint32_t*)ll;
                }
            }
        }
    } else {
#pragma unroll
        for (int mf = 0; mf < 2; mf++) {
#pragma unroll
            for (int nf = 0; nf < NF; nf++) {
                int col = n0w + nf * 8 + q * 2;
                if (col < N_DIM) {
                    float b0 = bias[col], b1 = bias[col + 1];
                    int row0 = m0 + m0w + mf * 16 + g;
#pragma unroll
                    for (int h2 = 0; h2 < 2; h2++) {
                        int row = row0 + h2 * 8;
                        float2 o;
                        o.x = acc[mf][nf][2 * h2 + 0] + b0;
                        o.y = acc[mf][nf][2 * h2 + 1] + b1;
                        *(float2*)(Of32 + (size_t)row * N_DIM + col) = o;
                    }
                }
            }
        }
    }
}

// ---------------------------------------------------------------------------
// ADMM v3: v2's math (dense 12 + fused +-identity box rows via Minv),
//          v1's memory placement (ALL y state in shared, stride 61).
//   Registers: only c[24], x[24], acc[24] (constant-indexed) — v1 footprint.
//   y layout per thread: [0..11]=yD, [12..35]=yI, [36..59]=yN.
//   Per-iter FMA ~1350 (vs v1's ~3120); per-iter LDS.128 ~290 (vs ~720).
// ---------------------------------------------------------------------------
#define ADMM_T 64
__global__ __launch_bounds__(ADMM_T) void admm_kernel(const float* __restrict__ raw,
                                                      float* __restrict__ out)
{
    __shared__ float sA[12 * N_DIM];       // dense A rows
    __shared__ float sG[12 * N_DIM];       // dense G rows
    __shared__ float sM[N_DIM * N_DIM];    // Minv rows
    __shared__ float sld[12], sud[12];     // dense bounds
    __shared__ float slb[N_DIM], sub_[N_DIM];  // box bounds
    __shared__ float sy[ADMM_T * 61];      // per-thread y (yD|yI|yN)

    const int tid = threadIdx.x;
    for (int s = tid; s < 12 * N_DIM; s += ADMM_T) { sA[s] = g_Atot[s]; sG[s] = g_G[s]; }
    for (int s = tid; s < N_DIM * N_DIM; s += ADMM_T) sM[s] = g_Minv[s];
    if (tid < 12) { sld[tid] = g_l[tid]; sud[tid] = g_u[tid]; }
    if (tid < N_DIM) { slb[tid] = g_l[12 + tid]; sub_[tid] = g_u[12 + tid]; }
    {
        float* myY0 = sy + tid * 61;
#pragma unroll
        for (int i = 0; i < 60; i++) myY0[i] = 0.0f;
    }
    __syncthreads();

    const int r = blockIdx.x * ADMM_T + tid;
    float* __restrict__ myY = sy + tid * 61;

    // c = raw_row @ Minv^T
    float rw[N_DIM];
#pragma unroll
    for (int q = 0; q < 6; q++) {
        float4 v = *(const float4*)(raw + (size_t)r * N_DIM + q * 4);
        rw[q * 4 + 0] = v.x; rw[q * 4 + 1] = v.y;
        rw[q * 4 + 2] = v.z; rw[q * 4 + 3] = v.w;
    }
    float c[N_DIM];
#pragma unroll
    for (int j = 0; j < N_DIM; j++) {
        float s0 = 0.f;
#pragma unroll
        for (int k = 0; k < N_DIM; k++)
            s0 += rw[k] * sM[j * N_DIM + k];
        c[j] = s0;
    }

    float acc[N_DIM], x[N_DIM];
#pragma unroll
    for (int j = 0; j < N_DIM; j++) acc[j] = 0.0f;

#pragma unroll 1
    for (int t = 0; t < 99; t++) {
#pragma unroll
        for (int j = 0; j < N_DIM; j++) { x[j] = c[j] + acc[j]; acc[j] = 0.0f; }

        // dense constraints (rows 0..11)
#pragma unroll 4
        for (int i = 0; i < 12; i++) {
            const float4* __restrict__ A4 = (const float4*)(sA + i * N_DIM);
            const float4* __restrict__ G4 = (const float4*)(sG + i * N_DIM);
            float z0 = 0.f, z1 = 0.f, z2 = 0.f, z3 = 0.f;
#pragma unroll
            for (int q = 0; q < 6; q++) {
                float4 a = A4[q];
                z0 += x[q * 4 + 0] * a.x; z1 += x[q * 4 + 1] * a.y;
                z2 += x[q * 4 + 2] * a.z; z3 += x[q * 4 + 3] * a.w;
            }
            float zt = (z0 + z1) + (z2 + z3);
            float v = zt + myY[i];
            float zn = fminf(fmaxf(v, sld[i]), sud[i]);
            myY[i] = v - zn;
            float w = 2.0f * zn - v;
#pragma unroll
            for (int q = 0; q < 6; q++) {
                float4 g = G4[q];
                acc[q * 4 + 0] += w * g.x; acc[q * 4 + 1] += w * g.y;
                acc[q * 4 + 2] += w * g.z; acc[q * 4 + 3] += w * g.w;
            }
        }

        // box constraints (I and -I rows) fused via Minv rows.
        // FULLY unrolled: x[j] must stay constant-indexed (register array).
#pragma unroll
        for (int j = 0; j < N_DIM; j++) {
            float lbj = slb[j], ubj = sub_[j];
            float v1 = x[j] + myY[12 + j];
            float zn1 = fminf(fmaxf(v1, lbj), ubj);
            myY[12 + j] = v1 - zn1;
            float wI = 2.0f * zn1 - v1;

            float v2 = myY[36 + j] - x[j];
            float zn2 = fminf(fmaxf(v2, -ubj), -lbj);
            myY[36 + j] = v2 - zn2;
            float wN = 2.0f * zn2 - v2;

            float d = wI - wN;
            const float4* __restrict__ M4 = (const float4*)(sM + j * N_DIM);
#pragma unroll
            for (int q = 0; q < 6; q++) {
                float4 m = M4[q];
                acc[q * 4 + 0] += d * m.x; acc[q * 4 + 1] += d * m.y;
                acc[q * 4 + 2] += d * m.z; acc[q * 4 + 3] += d * m.w;
            }
        }
    }

    // Final X (scan step 100)
#pragma unroll
    for (int q = 0; q < 6; q++) {
        float4 o;
        o.x = c[q * 4 + 0] + acc[q * 4 + 0];
        o.y = c[q * 4 + 1] + acc[q * 4 + 1];
        o.z = c[q * 4 + 2] + acc[q * 4 + 2];
        o.w = c[q * 4 + 3] + acc[q * 4 + 3];
        *(float4*)(out + (size_t)r * N_DIM + q * 4) = o;
    }
}

// ---------------------------------------------------------------------------
extern "C" void kernel_launch(void* const* d_in, const int* in_sizes, int n_in,
                              void* d_out, int out_size)
{
    (void)in_sizes; (void)n_in; (void)out_size;
    const float* state = (const float*)d_in[0];
    const float* Aeq   = (const float*)d_in[1];
    const float* beq   = (const float*)d_in[2];
    const float* Ain   = (const float*)d_in[3];
    const float* bin   = (const float*)d_in[4];
    const float* ub    = (const float*)d_in[5];
    const float* lb    = (const float*)d_in[6];
    const float* W1    = (const float*)d_in[7];
    const float* b1    = (const float*)d_in[8];
    const float* W2    = (const float*)d_in[9];
    const float* b2    = (const float*)d_in[10];
    const float* W3    = (const float*)d_in[11];
    const float* b3    = (const float*)d_in[12];
    float* out = (float*)d_out;

    __nv_bfloat16 *sh, *sl_, *h1h, *h1l, *h2h, *h2l;
    __nv_bfloat16 *w1h, *w1l, *w2h, *w2l, *w3h, *w3l;
    float* rawp;
    cudaGetSymbolAddress((void**)&sh,  g_sh);
    cudaGetSymbolAddress((void**)&sl_, g_sl);
    cudaGetSymbolAddress((void**)&h1h, g_h1h);
    cudaGetSymbolAddress((void**)&h1l, g_h1l);
    cudaGetSymbolAddress((void**)&h2h, g_h2h);
    cudaGetSymbolAddress((void**)&h2l, g_h2l);
    cudaGetSymbolAddress((void**)&w1h, g_w1h);
    cudaGetSymbolAddress((void**)&w1l, g_w1l);
    cudaGetSymbolAddress((void**)&w2h, g_w2h);
    cudaGetSymbolAddress((void**)&w2l, g_w2l);
    cudaGetSymbolAddress((void**)&w3h, g_w3h);
    cudaGetSymbolAddress((void**)&w3l, g_w3l);
    cudaGetSymbolAddress((void**)&rawp, g_raw);

    // smem: (Ah+Al)(128x64) + (Bh+Bl)(BNx64), bf16 — single buffered
    constexpr int SMEM_G12 = (2 * 128 * 64 + 2 * 128 * 64) * 2;  // 65536
    constexpr int SMEM_G3  = (2 * 128 * 64 + 2 * 32 * 64) * 2;   // 40960
    cudaFuncSetAttribute(gemm_mma<128, true>,
                         cudaFuncAttributeMaxDynamicSharedMemorySize, SMEM_G12);
    cudaFuncSetAttribute(gemm_mma<32, false>,
                         cudaFuncAttributeMaxDynamicSharedMemorySize, SMEM_G3);

    setup_kernel<<<1, 256>>>(Aeq, beq, Ain, bin, ub, lb);

    split_kernel<<<(B_ROWS * S_DIM / 4) / 256, 256>>>(state, sh, sl_);
    transpose_split<<<dim3(S_DIM / 32, H_DIM / 32), 256>>>(W1, w1h, w1l, S_DIM, H_DIM, H_DIM);
    transpose_split<<<dim3(H_DIM / 32, H_DIM / 32), 256>>>(W2, w2h, w2l, H_DIM, H_DIM, H_DIM);
    transpose_split<<<dim3(H_DIM / 32, 1),          256>>>(W3, w3h, w3l, H_DIM, N_DIM, 32);

    gemm_mma<128, true><<<dim3(H_DIM / 128, B_ROWS / 128), 256, SMEM_G12>>>(
        sh, sl_, w1h, w1l, b1, h1h, h1l, nullptr, S_DIM);
    gemm_mma<128, true><<<dim3(H_DIM / 128, B_ROWS / 128), 256, SMEM_G12>>>(
        h1h, h1l, w2h, w2l, b2, h2h, h2l, nullptr, H_DIM);
    gemm_mma<32, false><<<dim3(1, B_ROWS / 128), 256, SMEM_G3>>>(
        h2h, h2l, w3h, w3l, b3, nullptr, nullptr, rawp, H_DIM);

    admm_kernel<<<B_ROWS / ADMM_T, ADMM_T>>>(rawp, out);
}

// round 17
// speedup vs baseline: 1.3087x; 1.3087x over previous
#include <cuda_runtime.h>
#include <cuda_bf16.h>
#include <cstdint>

// Problem dims (fixed by the dataset)
#define B_ROWS 16384
#define S_DIM  512
#define H_DIM  1024
#define N_DIM  24
#define M_TOT  60      // 4 eq + 8 ineq + 24 (I) + 24 (-I)

// ---------------------------------------------------------------------------
// Device-global scratch (sanctioned: no allocation allowed)
// ---------------------------------------------------------------------------
__device__ __nv_bfloat16 g_sh[B_ROWS * S_DIM];
__device__ __nv_bfloat16 g_sl[B_ROWS * S_DIM];
__device__ __nv_bfloat16 g_h1h[B_ROWS * H_DIM];
__device__ __nv_bfloat16 g_h1l[B_ROWS * H_DIM];
__device__ __nv_bfloat16 g_h2h[B_ROWS * H_DIM];
__device__ __nv_bfloat16 g_h2l[B_ROWS * H_DIM];
__device__ __nv_bfloat16 g_w1h[H_DIM * S_DIM];
__device__ __nv_bfloat16 g_w1l[H_DIM * S_DIM];
__device__ __nv_bfloat16 g_w2h[H_DIM * H_DIM];
__device__ __nv_bfloat16 g_w2l[H_DIM * H_DIM];
__device__ __nv_bfloat16 g_w3h[32 * H_DIM];
__device__ __nv_bfloat16 g_w3l[32 * H_DIM];
__device__ float g_raw[B_ROWS * N_DIM];

// ADMM precomputed small matrices
__device__ float g_Atot[M_TOT * N_DIM];
__device__ float g_G[M_TOT * N_DIM];
__device__ float g_l[M_TOT];
__device__ float g_u[M_TOT];
__device__ float g_Minv[N_DIM * N_DIM];

// ---------------------------------------------------------------------------
// Helpers
// ---------------------------------------------------------------------------
__device__ __forceinline__ uint32_t smem_u32(const void* p) {
    uint32_t a;
    asm("{ .reg .u64 t; cvta.to.shared.u64 t, %1; cvt.u32.u64 %0, t; }"
        : "=r"(a) : "l"(p));
    return a;
}

#define SMEM_SWIZZLE_128B(x) ((x) ^ (((x) >> 3) & 0x70))

#define LDSM_X4(d0, d1, d2, d3, addr) \
    asm volatile("ldmatrix.sync.aligned.m8n8.x4.shared.b16 {%0,%1,%2,%3}, [%4];" \
        : "=r"(d0), "=r"(d1), "=r"(d2), "=r"(d3) : "r"(addr))

#define MMA_BF16(c, a, b) \
    asm volatile("mma.sync.aligned.m16n8k16.row.col.f32.bf16.bf16.f32 " \
        "{%0,%1,%2,%3}, {%4,%5,%6,%7}, {%8,%9}, {%0,%1,%2,%3};" \
        : "+f"((c)[0]), "+f"((c)[1]), "+f"((c)[2]), "+f"((c)[3]) \
        : "r"((a)[0]), "r"((a)[1]), "r"((a)[2]), "r"((a)[3]), \
          "r"((b)[0]), "r"((b)[1]))

__device__ __forceinline__ void split_bf16(float v, __nv_bfloat16& h, __nv_bfloat16& l) {
    h = __float2bfloat16(v);
    l = __float2bfloat16(v - __bfloat162float(h));
}

// ---------------------------------------------------------------------------
// Pre-pass 1: elementwise split fp32 -> (hi, lo) bf16
// ---------------------------------------------------------------------------
__global__ __launch_bounds__(256) void split_kernel(const float* __restrict__ X,
                                                    __nv_bfloat16* __restrict__ Xh,
                                                    __nv_bfloat16* __restrict__ Xl)
{
    int i = blockIdx.x * 256 + threadIdx.x;
    float4 v = ((const float4*)X)[i];
    __nv_bfloat16 h[4], l[4];
    split_bf16(v.x, h[0], l[0]); split_bf16(v.y, h[1], l[1]);
    split_bf16(v.z, h[2], l[2]); split_bf16(v.w, h[3], l[3]);
    ((uint2*)Xh)[i] = *(uint2*)h;
    ((uint2*)Xl)[i] = *(uint2*)l;
}

// ---------------------------------------------------------------------------
// Pre-pass 2: W [K x N] fp32 -> W^T [Npad x K] (hi, lo) bf16, zero-padded rows
// ---------------------------------------------------------------------------
__global__ __launch_bounds__(256) void transpose_split(const float* __restrict__ W,
                                                       __nv_bfloat16* __restrict__ Th,
                                                       __nv_bfloat16* __restrict__ Tl,
                                                       int K, int N, int Npad)
{
    __shared__ float t[32][33];
    int kb = blockIdx.x * 32, nb = blockIdx.y * 32;
    int tx = threadIdx.x & 31, ty = threadIdx.x >> 5;
#pragma unroll
    for (int i = 0; i < 32; i += 8) {
        int k = kb + ty + i, n = nb + tx;
        t[ty + i][tx] = (n < N) ? W[(size_t)k * N + n] : 0.0f;
    }
    __syncthreads();
#pragma unroll
    for (int i = 0; i < 32; i += 8) {
        int n = nb + ty + i, k = kb + tx;
        if (n < Npad) {
            float v = t[tx][ty + i];
            __nv_bfloat16 h, l;
            split_bf16(v, h, l);
            Th[(size_t)n * K + k] = h;
            Tl[(size_t)n * K + k] = l;
        }
    }
}

// ---------------------------------------------------------------------------
// Setup (unchanged — proven)
// ---------------------------------------------------------------------------
__global__ __launch_bounds__(256) void setup_kernel(const float* __restrict__ Aeq,
                             const float* __restrict__ beq,
                             const float* __restrict__ Ain,
                             const float* __restrict__ bin,
                             const float* __restrict__ ub,
                             const float* __restrict__ lb)
{
    __shared__ float At[M_TOT * N_DIM];
    __shared__ float Maug[24][49];
    const int tid = threadIdx.x;

    for (int s = tid; s < M_TOT * N_DIM; s += 256) {
        int i = s / N_DIM, j = s % N_DIM;
        float v;
        if (i < 4)       v = Aeq[i * N_DIM + j];
        else if (i < 12) v = Ain[(i - 4) * N_DIM + j];
        else if (i < 36) v = (j == i - 12) ? 1.0f : 0.0f;
        else             v = (j == i - 36) ? -1.0f : 0.0f;
        At[s] = v;
        g_Atot[s] = v;
    }
    if (tid < M_TOT) {
        int i = tid;
        float lv, uv;
        const float NEG_INF = __int_as_float(0xff800000);
        if (i < 4)       { lv = beq[i];        uv = beq[i]; }
        else if (i < 12) { lv = NEG_INF;       uv = bin[i - 4]; }
        else if (i < 36) { lv = lb[i - 12];    uv = ub[i - 12]; }
        else             { lv = -ub[i - 36];   uv = -lb[i - 36]; }
        g_l[i] = lv; g_u[i] = uv;
    }
    __syncthreads();

    for (int s = tid; s < N_DIM * N_DIM; s += 256) {
        int j = s / N_DIM, k = s % N_DIM;
        float sum = 0.0f;
        for (int i = 0; i < M_TOT; i++)
            sum += At[i * N_DIM + j] * At[i * N_DIM + k];
        if (j == k) sum += 1.0f + 1e-6f;
        Maug[j][k] = sum;
        Maug[j][24 + k] = (j == k) ? 1.0f : 0.0f;
    }
    __syncthreads();

    for (int k = 0; k < 24; k++) {
        if (tid == 0) {
            float piv = 1.0f / Maug[k][k];
            for (int c = 0; c < 48; c++) Maug[k][c] *= piv;
        }
        __syncthreads();
        if (tid < 24 && tid != k) {
            float f = Maug[tid][k];
            for (int c = 0; c < 48; c++) Maug[tid][c] -= f * Maug[k][c];
        }
        __syncthreads();
    }

    for (int s = tid; s < N_DIM * N_DIM; s += 256)
        g_Minv[s] = Maug[s / N_DIM][24 + (s % N_DIM)];

    for (int s = tid; s < M_TOT * N_DIM; s += 256) {
        int i = s / N_DIM, j = s % N_DIM;
        float sum = 0.0f;
        for (int k = 0; k < 24; k++)
            sum += At[i * N_DIM + k] * Maug[j][24 + k];
        g_G[s] = sum;
    }
}

// ---------------------------------------------------------------------------
// HMMA GEMM (mma.sync.m16n8k16 bf16), 2-split / 3-product, fp32 reg accum.
//   R15 proven version: LDG->reg->STS double buffering, single smem buffer.
// ---------------------------------------------------------------------------
template <int BN, bool RELUSPLIT>
__global__ __launch_bounds__(256) void gemm_mma(
    const __nv_bfloat16* __restrict__ Ahi, const __nv_bfloat16* __restrict__ Alo,
    const __nv_bfloat16* __restrict__ Bhi, const __nv_bfloat16* __restrict__ Blo,
    const float* __restrict__ bias,
    __nv_bfloat16* __restrict__ Ohi, __nv_bfloat16* __restrict__ Olo,
    float* __restrict__ Of32,
    int K)
{
    extern __shared__ __align__(1024) char sm[];
    constexpr int NF = BN / 16;
    constexpr int NBI = BN / 32;                       // B-tile iters per split
    __nv_bfloat16* As_h = (__nv_bfloat16*)sm;          // 128 x 64
    __nv_bfloat16* As_l = As_h + 128 * 64;
    __nv_bfloat16* Bs_h = As_l + 128 * 64;             // BN x 64
    __nv_bfloat16* Bs_l = Bs_h + BN * 64;

    const int tid  = threadIdx.x;
    const int wid  = tid >> 5;
    const int lane = tid & 31;
    const int m0 = blockIdx.y * 128;
    const int n0 = blockIdx.x * BN;
    const int m0w = (wid >> 1) * 32;
    const int n0w = (wid & 1) * (BN / 2);

    const uint32_t sAh = smem_u32(As_h), sAl = smem_u32(As_l);
    const uint32_t sBh = smem_u32(Bs_h), sBl = smem_u32(Bs_l);

    float acc[2][NF][4];
#pragma unroll
    for (int mf = 0; mf < 2; mf++)
#pragma unroll
        for (int nf = 0; nf < NF; nf++)
#pragma unroll
            for (int e = 0; e < 4; e++) acc[mf][nf][e] = 0.0f;

    const int r  = lane & 7;
    const int ms = lane >> 3;

    // per-thread staging registers for the next chunk
    uint4 ra_h[4], ra_l[4], rb_h[NBI], rb_l[NBI];

    auto ldg_chunk = [&](int kt) {
#pragma unroll
        for (int it = 0; it < 4; it++) {
            int idx = tid + it * 256;
            int row = idx >> 3, s16 = idx & 7;
            size_t g = (size_t)(m0 + row) * K + kt + s16 * 8;
            ra_h[it] = *(const uint4*)(Ahi + g);
            ra_l[it] = *(const uint4*)(Alo + g);
        }
#pragma unroll
        for (int it = 0; it < NBI; it++) {
            int idx = tid + it * 256;
            int row = idx >> 3, s16 = idx & 7;
            size_t g = (size_t)(n0 + row) * K + kt + s16 * 8;
            rb_h[it] = *(const uint4*)(Bhi + g);
            rb_l[it] = *(const uint4*)(Blo + g);
        }
    };

    auto sts_chunk = [&]() {
#pragma unroll
        for (int it = 0; it < 4; it++) {
            int idx = tid + it * 256;
            int row = idx >> 3, s16 = idx & 7;
            uint32_t off = SMEM_SWIZZLE_128B((uint32_t)(row * 128 + s16 * 16));
            *(uint4*)((char*)As_h + off) = ra_h[it];
            *(uint4*)((char*)As_l + off) = ra_l[it];
        }
#pragma unroll
        for (int it = 0; it < NBI; it++) {
            int idx = tid + it * 256;
            int row = idx >> 3, s16 = idx & 7;
            uint32_t off = SMEM_SWIZZLE_128B((uint32_t)(row * 128 + s16 * 16));
            *(uint4*)((char*)Bs_h + off) = rb_h[it];
            *(uint4*)((char*)Bs_l + off) = rb_l[it];
        }
    };

    ldg_chunk(0);

    for (int kt = 0; kt < K; kt += 64) {
        sts_chunk();
        __syncthreads();
        if (kt + 64 < K)
            ldg_chunk(kt + 64);   // issued now, consumed by STS next iter

#pragma unroll
        for (int ks = 0; ks < 4; ks++) {
            uint32_t a_h[2][4], a_l[2][4], bfr[NF][2];
#pragma unroll
            for (int mf = 0; mf < 2; mf++) {
                int row = m0w + mf * 16 + (ms & 1) * 8 + r;
                int seg = 2 * ks + (ms >> 1);
                uint32_t off = SMEM_SWIZZLE_128B((uint32_t)(row * 128 + seg * 16));
                LDSM_X4(a_h[mf][0], a_h[mf][1], a_h[mf][2], a_h[mf][3], sAh + off);
                LDSM_X4(a_l[mf][0], a_l[mf][1], a_l[mf][2], a_l[mf][3], sAl + off);
            }
#pragma unroll
            for (int g2 = 0; g2 < NF / 2; g2++) {
                int row = n0w + g2 * 16 + (ms >> 1) * 8 + r;
                int seg = 2 * ks + (ms & 1);
                uint32_t off = SMEM_SWIZZLE_128B((uint32_t)(row * 128 + seg * 16));
                LDSM_X4(bfr[2 * g2][0], bfr[2 * g2][1],
                        bfr[2 * g2 + 1][0], bfr[2 * g2 + 1][1], sBh + off);
            }
#pragma unroll
            for (int mf = 0; mf < 2; mf++)
#pragma unroll
                for (int nf = 0; nf < NF; nf++)
                    MMA_BF16(acc[mf][nf], a_h[mf], bfr[nf]);
#pragma unroll
            for (int mf = 0; mf < 2; mf++)
#pragma unroll
                for (int nf = 0; nf < NF; nf++)
                    MMA_BF16(acc[mf][nf], a_l[mf], bfr[nf]);
#pragma unroll
            for (int g2 = 0; g2 < NF / 2; g2++) {
                int row = n0w + g2 * 16 + (ms >> 1) * 8 + r;
                int seg = 2 * ks + (ms & 1);
                uint32_t off = SMEM_SWIZZLE_128B((uint32_t)(row * 128 + seg * 16));
                LDSM_X4(bfr[2 * g2][0], bfr[2 * g2][1],
                        bfr[2 * g2 + 1][0], bfr[2 * g2 + 1][1], sBl + off);
            }
#pragma unroll
            for (int mf = 0; mf < 2; mf++)
#pragma unroll
                for (int nf = 0; nf < NF; nf++)
                    MMA_BF16(acc[mf][nf], a_h[mf], bfr[nf]);
        }
        __syncthreads();
    }

    // ---- epilogue ----
    const int g = lane >> 2, q = lane & 3;
    if (RELUSPLIT) {
#pragma unroll
        for (int mf = 0; mf < 2; mf++) {
#pragma unroll
            for (int nf = 0; nf < NF; nf++) {
                int col = n0 + n0w + nf * 8 + q * 2;
                float b0 = bias[col], b1 = bias[col + 1];
                int row0 = m0 + m0w + mf * 16 + g;
#pragma unroll
                for (int h2 = 0; h2 < 2; h2++) {
                    int row = row0 + h2 * 8;
                    float v0 = fmaxf(acc[mf][nf][2 * h2 + 0] + b0, 0.0f);
                    float v1 = fmaxf(acc[mf][nf][2 * h2 + 1] + b1, 0.0f);
                    __nv_bfloat16 hh[2], ll[2];
                    split_bf16(v0, hh[0], ll[0]);
                    split_bf16(v1, hh[1], ll[1]);
                    size_t o = (size_t)row * H_DIM + col;
                    *(uint32_t*)(Ohi + o) = *(uint32_t*)hh;
                    *(uint32_t*)(Olo + o) = *(uint32_t*)ll;
                }
            }
        }
    } else {
#pragma unroll
        for (int mf = 0; mf < 2; mf++) {
#pragma unroll
            for (int nf = 0; nf < NF; nf++) {
                int col = n0w + nf * 8 + q * 2;
                if (col < N_DIM) {
                    float b0 = bias[col], b1 = bias[col + 1];
                    int row0 = m0 + m0w + mf * 16 + g;
#pragma unroll
                    for (int h2 = 0; h2 < 2; h2++) {
                        int row = row0 + h2 * 8;
                        float2 o;
                        o.x = acc[mf][nf][2 * h2 + 0] + b0;
                        o.y = acc[mf][nf][2 * h2 + 1] + b1;
                        *(float2*)(Of32 + (size_t)row * N_DIM + col) = o;
                    }
                }
            }
        }
    }
}

// ---------------------------------------------------------------------------
// ADMM v4: v1's exact per-constraint structure, but each batch row is handled
// by a LANE PAIR (even lane: constraints 0..29, odd lane: 30..59).
//   - per-iteration acc merged across the pair with one __shfl_xor per comp.
//   - y: 30 floats per thread in shared (stride 31, odd -> conflict-free).
//   - registers: c[24], x[24], acc[24] only (v1 footprint, no spill).
//   Serial FMA per thread per iter: 2880 -> 1440 (+24 shfl).
// ---------------------------------------------------------------------------
#define ADMM_T 128   // 64 rows per block, 2 lanes per row
__global__ __launch_bounds__(ADMM_T) void admm_kernel(const float* __restrict__ raw,
                                                      float* __restrict__ out)
{
    __shared__ float sA[M_TOT * N_DIM];
    __shared__ float sG[M_TOT * N_DIM];
    __shared__ float sl[M_TOT], su[M_TOT];
    __shared__ float sMinv[N_DIM * N_DIM];
    __shared__ float sy[ADMM_T * 31];

    const int tid = threadIdx.x;
    for (int s = tid; s < M_TOT * N_DIM; s += ADMM_T) { sA[s] = g_Atot[s]; sG[s] = g_G[s]; }
    for (int s = tid; s < N_DIM * N_DIM; s += ADMM_T) sMinv[s] = g_Minv[s];
    for (int s = tid; s < M_TOT; s += ADMM_T) { sl[s] = g_l[s]; su[s] = g_u[s]; }
    {
        float* myY0 = sy + tid * 31;
#pragma unroll
        for (int i = 0; i < 30; i++) myY0[i] = 0.0f;
    }
    __syncthreads();

    const int half = tid & 1;                       // which 30 constraints
    const int base = half * 30;
    const int r = blockIdx.x * (ADMM_T / 2) + (tid >> 1);
    float* __restrict__ myY = sy + tid * 31;

    // Prologue: both lanes of a pair load the same raw row, compute same c.
    float rw[N_DIM];
#pragma unroll
    for (int q = 0; q < 6; q++) {
        float4 v = *(const float4*)(raw + (size_t)r * N_DIM + q * 4);
        rw[q * 4 + 0] = v.x; rw[q * 4 + 1] = v.y;
        rw[q * 4 + 2] = v.z; rw[q * 4 + 3] = v.w;
    }
    float c[N_DIM];
#pragma unroll
    for (int j = 0; j < N_DIM; j++) {
        float s0 = 0.f;
#pragma unroll
        for (int k = 0; k < N_DIM; k++)
            s0 += rw[k] * sMinv[j * N_DIM + k];
        c[j] = s0;
    }

    float acc[N_DIM];
    float x[N_DIM];
#pragma unroll
    for (int j = 0; j < N_DIM; j++) acc[j] = 0.0f;

#pragma unroll 1
    for (int t = 0; t < 99; t++) {
        // merge pair partial acc, form x, reset acc
#pragma unroll
        for (int j = 0; j < N_DIM; j++) {
            float a2 = acc[j] + __shfl_xor_sync(0xffffffffu, acc[j], 1);
            x[j] = c[j] + a2;
            acc[j] = 0.0f;
        }
#pragma unroll 5
        for (int i = 0; i < 30; i++) {
            const int ii = base + i;
            const float4* __restrict__ A4 = (const float4*)(sA + ii * N_DIM);
            const float4* __restrict__ G4 = (const float4*)(sG + ii * N_DIM);
            float z0 = 0.f, z1 = 0.f, z2 = 0.f, z3 = 0.f;
#pragma unroll
            for (int q = 0; q < 6; q++) {
                float4 a = A4[q];
                z0 += x[q * 4 + 0] * a.x; z1 += x[q * 4 + 1] * a.y;
                z2 += x[q * 4 + 2] * a.z; z3 += x[q * 4 + 3] * a.w;
            }
            float zt = (z0 + z1) + (z2 + z3);
            float v = zt + myY[i];
            float zn = fminf(fmaxf(v, sl[ii]), su[ii]);
            myY[i] = v - zn;
            float w = 2.0f * zn - v;
#pragma unroll
            for (int q = 0; q < 6; q++) {
                float4 g = G4[q];
                acc[q * 4 + 0] += w * g.x; acc[q * 4 + 1] += w * g.y;
                acc[q * 4 + 2] += w * g.z; acc[q * 4 + 3] += w * g.w;
            }
        }
    }

    // Final X (scan step 100): merge, even lane writes.
    float xf[N_DIM];
#pragma unroll
    for (int j = 0; j < N_DIM; j++) {
        float a2 = acc[j] + __shfl_xor_sync(0xffffffffu, acc[j], 1);
        xf[j] = c[j] + a2;
    }
    if (half == 0) {
#pragma unroll
        for (int q = 0; q < 6; q++) {
            float4 o;
            o.x = xf[q * 4 + 0]; o.y = xf[q * 4 + 1];
            o.z = xf[q * 4 + 2]; o.w = xf[q * 4 + 3];
            *(float4*)(out + (size_t)r * N_DIM + q * 4) = o;
        }
    }
}

// ---------------------------------------------------------------------------
extern "C" void kernel_launch(void* const* d_in, const int* in_sizes, int n_in,
                              void* d_out, int out_size)
{
    (void)in_sizes; (void)n_in; (void)out_size;
    const float* state = (const float*)d_in[0];
    const float* Aeq   = (const float*)d_in[1];
    const float* beq   = (const float*)d_in[2];
    const float* Ain   = (const float*)d_in[3];
    const float* bin   = (const float*)d_in[4];
    const float* ub    = (const float*)d_in[5];
    const float* lb    = (const float*)d_in[6];
    const float* W1    = (const float*)d_in[7];
    const float* b1    = (const float*)d_in[8];
    const float* W2    = (const float*)d_in[9];
    const float* b2    = (const float*)d_in[10];
    const float* W3    = (const float*)d_in[11];
    const float* b3    = (const float*)d_in[12];
    float* out = (float*)d_out;

    __nv_bfloat16 *sh, *sl_, *h1h, *h1l, *h2h, *h2l;
    __nv_bfloat16 *w1h, *w1l, *w2h, *w2l, *w3h, *w3l;
    float* rawp;
    cudaGetSymbolAddress((void**)&sh,  g_sh);
    cudaGetSymbolAddress((void**)&sl_, g_sl);
    cudaGetSymbolAddress((void**)&h1h, g_h1h);
    cudaGetSymbolAddress((void**)&h1l, g_h1l);
    cudaGetSymbolAddress((void**)&h2h, g_h2h);
    cudaGetSymbolAddress((void**)&h2l, g_h2l);
    cudaGetSymbolAddress((void**)&w1h, g_w1h);
    cudaGetSymbolAddress((void**)&w1l, g_w1l);
    cudaGetSymbolAddress((void**)&w2h, g_w2h);
    cudaGetSymbolAddress((void**)&w2l, g_w2l);
    cudaGetSymbolAddress((void**)&w3h, g_w3h);
    cudaGetSymbolAddress((void**)&w3l, g_w3l);
    cudaGetSymbolAddress((void**)&rawp, g_raw);

    // smem: (Ah+Al)(128x64) + (Bh+Bl)(BNx64), bf16 — single buffered
    constexpr int SMEM_G12 = (2 * 128 * 64 + 2 * 128 * 64) * 2;  // 65536
    constexpr int SMEM_G3  = (2 * 128 * 64 + 2 * 32 * 64) * 2;   // 40960
    cudaFuncSetAttribute(gemm_mma<128, true>,
                         cudaFuncAttributeMaxDynamicSharedMemorySize, SMEM_G12);
    cudaFuncSetAttribute(gemm_mma<32, false>,
                         cudaFuncAttributeMaxDynamicSharedMemorySize, SMEM_G3);

    setup_kernel<<<1, 256>>>(Aeq, beq, Ain, bin, ub, lb);

    split_kernel<<<(B_ROWS * S_DIM / 4) / 256, 256>>>(state, sh, sl_);
    transpose_split<<<dim3(S_DIM / 32, H_DIM / 32), 256>>>(W1, w1h, w1l, S_DIM, H_DIM, H_DIM);
    transpose_split<<<dim3(H_DIM / 32, H_DIM / 32), 256>>>(W2, w2h, w2l, H_DIM, H_DIM, H_DIM);
    transpose_split<<<dim3(H_DIM / 32, 1),          256>>>(W3, w3h, w3l, H_DIM, N_DIM, 32);

    gemm_mma<128, true><<<dim3(H_DIM / 128, B_ROWS / 128), 256, SMEM_G12>>>(
        sh, sl_, w1h, w1l, b1, h1h, h1l, nullptr, S_DIM);
    gemm_mma<128, true><<<dim3(H_DIM / 128, B_ROWS / 128), 256, SMEM_G12>>>(
        h1h, h1l, w2h, w2l, b2, h2h, h2l, nullptr, H_DIM);
    gemm_mma<32, false><<<dim3(1, B_ROWS / 128), 256, SMEM_G3>>>(
        h2h, h2l, w3h, w3l, b3, nullptr, nullptr, rawp, H_DIM);

    admm_kernel<<<B_ROWS / (ADMM_T / 2), ADMM_T>>>(rawp, out);
}